// round 1
// baseline (speedup 1.0000x reference)
#include <cuda_runtime.h>

// SparseGCN / LightGCN: 3x COO SpMM over N=150000 nodes, D=64, nnz=4.8M.
// out = [emb0 (N*D floats) | light_out (N*D floats)]

#define U_ROWS 100000
#define I_ROWS 50000
#define N_NODES (U_ROWS + I_ROWS)
#define EMB_D 64
#define TOTAL_F (N_NODES * EMB_D)     // 9,600,000 floats
#define TOTAL_V4 (TOTAL_F / 4)        // 2,400,000 float4

// Scratch (static __device__ — allocation is forbidden in kernel_launch).
__device__ float g_bufA[TOTAL_F];   // ping
__device__ float g_bufB[TOTAL_F];   // pong
__device__ float g_acc[TOTAL_F];    // running sum emb0 + y1 + y2 (+ y3 fused in final)

// ---------------------------------------------------------------------------
// init: g_bufA = acc = emb0 = concat(user, item); out[0:TOTAL_F] = emb0;
//       g_bufB = 0 (target of first SpMM)
// ---------------------------------------------------------------------------
__global__ void init_kernel(const float4* __restrict__ u,
                            const float4* __restrict__ it,
                            float4* __restrict__ out) {
    int i = blockIdx.x * blockDim.x + threadIdx.x;
    if (i >= TOTAL_V4) return;
    const int u_v4 = U_ROWS * EMB_D / 4;
    float4 v = (i < u_v4) ? u[i] : it[i - u_v4];
    ((float4*)g_bufA)[i] = v;
    ((float4*)g_acc)[i]  = v;
    out[i] = v;
    ((float4*)g_bufB)[i] = make_float4(0.f, 0.f, 0.f, 0.f);
}

// ---------------------------------------------------------------------------
// spmm: y[row] += val * x[col], 16 threads per edge (one float4 each).
// dir==0: x=g_bufA, y=g_bufB ; dir==1: x=g_bufB, y=g_bufA
// ---------------------------------------------------------------------------
__global__ void spmm_kernel(int dir,
                            const int*   __restrict__ rows,
                            const int*   __restrict__ cols,
                            const float* __restrict__ vals,
                            int nnz) {
    const float* __restrict__ x = dir ? g_bufB : g_bufA;
    float*       __restrict__ y = dir ? g_bufA : g_bufB;

    unsigned long long gid = (unsigned long long)blockIdx.x * blockDim.x + threadIdx.x;
    int e = (int)(gid >> 4);
    int c = (int)(gid & 15);
    if (e >= nnz) return;

    int   r   = __ldg(rows + e);
    int   col = __ldg(cols + e);
    float v   = __ldg(vals + e);

    float4 xv = ((const float4*)x)[col * 16 + c];
    xv.x *= v; xv.y *= v; xv.z *= v; xv.w *= v;

    float* dst = y + ((long long)r * EMB_D + c * 4);
    asm volatile("red.global.add.v4.f32 [%0], {%1,%2,%3,%4};"
                 :: "l"(dst), "f"(xv.x), "f"(xv.y), "f"(xv.z), "f"(xv.w)
                 : "memory");
}

// ---------------------------------------------------------------------------
// acc_zero: acc += (just-produced layer output); zero the buffer that is the
// NEXT SpMM target. mode==0: acc+=bufB, zero bufA ; mode==1: acc+=bufA, zero bufB
// ---------------------------------------------------------------------------
__global__ void acc_zero_kernel(int mode) {
    int i = blockIdx.x * blockDim.x + threadIdx.x;
    if (i >= TOTAL_V4) return;
    float4* accv = (float4*)g_acc;
    if (mode == 0) {
        float4 yv = ((const float4*)g_bufB)[i];
        float4 a  = accv[i];
        a.x += yv.x; a.y += yv.y; a.z += yv.z; a.w += yv.w;
        accv[i] = a;
        ((float4*)g_bufA)[i] = make_float4(0.f, 0.f, 0.f, 0.f);
    } else {
        float4 yv = ((const float4*)g_bufA)[i];
        float4 a  = accv[i];
        a.x += yv.x; a.y += yv.y; a.z += yv.z; a.w += yv.w;
        accv[i] = a;
        ((float4*)g_bufB)[i] = make_float4(0.f, 0.f, 0.f, 0.f);
    }
}

// ---------------------------------------------------------------------------
// final: light_out = (acc + y3) / 4 ; y3 lives in g_bufB (layer-3 target)
// ---------------------------------------------------------------------------
__global__ void final_kernel(float4* __restrict__ out2) {
    int i = blockIdx.x * blockDim.x + threadIdx.x;
    if (i >= TOTAL_V4) return;
    float4 a = ((const float4*)g_acc)[i];
    float4 y = ((const float4*)g_bufB)[i];
    float4 o;
    o.x = (a.x + y.x) * 0.25f;
    o.y = (a.y + y.y) * 0.25f;
    o.z = (a.z + y.z) * 0.25f;
    o.w = (a.w + y.w) * 0.25f;
    out2[i] = o;
}

extern "C" void kernel_launch(void* const* d_in, const int* in_sizes, int n_in,
                              void* d_out, int out_size) {
    const float* user_emb = (const float*)d_in[0];
    const float* item_emb = (const float*)d_in[1];
    const float* edge_val = (const float*)d_in[2];
    const int*   edge_row = (const int*)d_in[3];
    const int*   edge_col = (const int*)d_in[4];
    const int nnz = in_sizes[2];

    float* out = (float*)d_out;

    const int TPB = 256;
    const int ew_blocks = (int)(((unsigned long long)nnz * 16 + TPB - 1) / TPB);
    const int nd_blocks = (TOTAL_V4 + TPB - 1) / TPB;

    // init: emb0 -> bufA, acc, out[0:TOTAL_F]; bufB = 0
    init_kernel<<<nd_blocks, TPB>>>((const float4*)user_emb,
                                    (const float4*)item_emb,
                                    (float4*)out);

    // layer 1: bufB += A @ bufA ; acc += bufB ; zero bufA
    spmm_kernel<<<ew_blocks, TPB>>>(0, edge_row, edge_col, edge_val, nnz);
    acc_zero_kernel<<<nd_blocks, TPB>>>(0);

    // layer 2: bufA += A @ bufB ; acc += bufA ; zero bufB
    spmm_kernel<<<ew_blocks, TPB>>>(1, edge_row, edge_col, edge_val, nnz);
    acc_zero_kernel<<<nd_blocks, TPB>>>(1);

    // layer 3: bufB += A @ bufA ; out2 = (acc + bufB) / 4
    spmm_kernel<<<ew_blocks, TPB>>>(0, edge_row, edge_col, edge_val, nnz);
    final_kernel<<<nd_blocks, TPB>>>((float4*)(out + TOTAL_F));
}

// round 3
// speedup vs baseline: 2.3236x; 2.3236x over previous
#include <cuda_runtime.h>

// LightGCN 3-layer: padded-ELL build (once) + 3x warp-per-row SpMM, epilogues fused.
// out = [emb0 (N*D) | (emb0+y1+y2+y3)/4]
// All scratch lives in __device__ globals referenced ONLY from device code
// (passing __device__ symbols as host-side kernel args is UB -- round-2 bug).

#define U_ROWS 100000
#define I_ROWS 50000
#define N_NODES (U_ROWS + I_ROWS)
#define EMB_D 64
#define TOTAL_F (N_NODES * EMB_D)
#define TOTAL_V4 (TOTAL_F / 4)
#define PAD 128
#define SPILL_MAX (1 << 20)

__device__ float g_bufA[TOTAL_F];
__device__ float g_bufB[TOTAL_F];
__device__ float g_acc[TOTAL_F];
__device__ int2  g_slots[(size_t)N_NODES * PAD];   // {col, val-as-int}
__device__ int   g_cnt[N_NODES];
__device__ int   g_spill[SPILL_MAX];
__device__ int   g_spill_cnt;

// ---------------------------------------------------------------------------
// init: bufA = acc = emb0; out[0:TOTAL_F] = emb0; cnt = 0; spill_cnt = 0
// ---------------------------------------------------------------------------
__global__ void init_kernel(const float4* __restrict__ u,
                            const float4* __restrict__ it,
                            float4* __restrict__ out) {
    int i = blockIdx.x * blockDim.x + threadIdx.x;
    if (i == 0) g_spill_cnt = 0;
    if (i < N_NODES) g_cnt[i] = 0;
    if (i >= TOTAL_V4) return;
    const int u_v4 = U_ROWS * EMB_D / 4;
    float4 v = (i < u_v4) ? u[i] : it[i - u_v4];
    ((float4*)g_bufA)[i] = v;
    ((float4*)g_acc)[i]  = v;
    out[i] = v;
}

// ---------------------------------------------------------------------------
// build: scatter each edge into its row's ELL bucket (order-free, no scan)
// ---------------------------------------------------------------------------
__global__ void build_kernel(const int*   __restrict__ rows,
                             const int*   __restrict__ cols,
                             const float* __restrict__ vals,
                             int nnz) {
    int e = blockIdx.x * blockDim.x + threadIdx.x;
    if (e >= nnz) return;
    int r = rows[e];
    int pos = atomicAdd(&g_cnt[r], 1);
    if (pos < PAD) {
        g_slots[(size_t)r * PAD + pos] = make_int2(cols[e], __float_as_int(vals[e]));
    } else {
        int s = atomicAdd(&g_spill_cnt, 1);
        if (s < SPILL_MAX) g_spill[s] = e;
    }
}

// ---------------------------------------------------------------------------
// spmm: one warp per row, no atomics. y[r] = sum val * x[col].
//   mode 0: x=bufA, y->bufB, acc += y
//   mode 1: x=bufB, y->bufA, acc += y
//   mode 2: x=bufA, out2[r] = (acc[r] + y) * 0.25   (y not stored)
// ---------------------------------------------------------------------------
__global__ __launch_bounds__(256) void spmm_ell_kernel(int mode,
                                                       float2* __restrict__ out2) {
    int gw   = (blockIdx.x * blockDim.x + threadIdx.x) >> 5;
    int lane = threadIdx.x & 31;
    if (gw >= N_NODES) return;

    const float2* __restrict__ xv2 =
        (mode == 1) ? (const float2*)g_bufB : (const float2*)g_bufA;

    int cnt = g_cnt[gw];
    cnt = min(cnt, PAD);
    const int2* sl = g_slots + (size_t)gw * PAD;

    float ax = 0.f, ay = 0.f;
    int base = 0;
    for (; base + 32 <= cnt; base += 32) {
        int2 s = sl[base + lane];
        #pragma unroll
        for (int k = 0; k < 32; k++) {
            int   c = __shfl_sync(0xffffffffu, s.x, k);
            float v = __int_as_float(__shfl_sync(0xffffffffu, s.y, k));
            float2 xv = xv2[c * 32 + lane];
            ax = fmaf(v, xv.x, ax);
            ay = fmaf(v, xv.y, ay);
        }
    }
    int rem = cnt - base;
    if (rem > 0) {
        int2 s = (lane < rem) ? sl[base + lane] : make_int2(0, 0);
        #pragma unroll 4
        for (int k = 0; k < rem; k++) {
            int   c = __shfl_sync(0xffffffffu, s.x, k);
            float v = __int_as_float(__shfl_sync(0xffffffffu, s.y, k));
            float2 xv = xv2[c * 32 + lane];
            ax = fmaf(v, xv.x, ax);
            ay = fmaf(v, xv.y, ay);
        }
    }

    int off = gw * 32 + lane;
    if (mode == 2) {
        float2 a = ((const float2*)g_acc)[off];
        out2[off] = make_float2((a.x + ax) * 0.25f, (a.y + ay) * 0.25f);
    } else {
        float2* y_out = (mode == 0) ? (float2*)g_bufB : (float2*)g_bufA;
        y_out[off] = make_float2(ax, ay);
        float2 a = ((float2*)g_acc)[off];
        ((float2*)g_acc)[off] = make_float2(a.x + ax, a.y + ay);
    }
}

// ---------------------------------------------------------------------------
// spill: ELL-overflow edges (statistically never runs; correctness net).
//   mode 0: x=bufA; bufB[r]+=d; acc[r]+=d
//   mode 1: x=bufB; bufA[r]+=d; acc[r]+=d
//   mode 2: x=bufA; out2[r] += d*0.25
// ---------------------------------------------------------------------------
__global__ void spill_kernel(int mode,
                             const int*   __restrict__ rows,
                             const int*   __restrict__ cols,
                             const float* __restrict__ vals,
                             float* __restrict__ out2) {
    int n = g_spill_cnt;
    if (n > SPILL_MAX) n = SPILL_MAX;
    const float* x = (mode == 1) ? g_bufB : g_bufA;
    for (int s = blockIdx.x * blockDim.x + threadIdx.x; s < n;
         s += gridDim.x * blockDim.x) {
        int e = g_spill[s];
        int r = rows[e], c = cols[e];
        float v = vals[e];
        for (int d = 0; d < EMB_D; d++) {
            float delta = v * x[c * EMB_D + d];
            if (mode == 0) {
                atomicAdd(&g_bufB[r * EMB_D + d], delta);
                atomicAdd(&g_acc[r * EMB_D + d], delta);
            } else if (mode == 1) {
                atomicAdd(&g_bufA[r * EMB_D + d], delta);
                atomicAdd(&g_acc[r * EMB_D + d], delta);
            } else {
                atomicAdd(&out2[r * EMB_D + d], delta * 0.25f);
            }
        }
    }
}

extern "C" void kernel_launch(void* const* d_in, const int* in_sizes, int n_in,
                              void* d_out, int out_size) {
    const float* user_emb = (const float*)d_in[0];
    const float* item_emb = (const float*)d_in[1];
    const float* edge_val = (const float*)d_in[2];
    const int*   edge_row = (const int*)d_in[3];
    const int*   edge_col = (const int*)d_in[4];
    const int nnz = in_sizes[2];

    float* out  = (float*)d_out;
    float* out2 = out + TOTAL_F;

    const int TPB = 256;
    const int init_blocks  = (TOTAL_V4 + TPB - 1) / TPB;
    const int build_blocks = (nnz + TPB - 1) / TPB;
    const int spmm_blocks  = (N_NODES * 32 + TPB - 1) / TPB;  // warp per row

    init_kernel<<<init_blocks, TPB>>>((const float4*)user_emb,
                                      (const float4*)item_emb,
                                      (float4*)out);

    build_kernel<<<build_blocks, TPB>>>(edge_row, edge_col, edge_val, nnz);

    // layer 1: x=bufA -> y=bufB, acc += y
    spmm_ell_kernel<<<spmm_blocks, TPB>>>(0, nullptr);
    spill_kernel<<<16, TPB>>>(0, edge_row, edge_col, edge_val, nullptr);

    // layer 2: x=bufB -> y=bufA, acc += y
    spmm_ell_kernel<<<spmm_blocks, TPB>>>(1, nullptr);
    spill_kernel<<<16, TPB>>>(1, edge_row, edge_col, edge_val, nullptr);

    // layer 3: x=bufA -> out2 = (acc + y)/4
    spmm_ell_kernel<<<spmm_blocks, TPB>>>(2, (float2*)out2);
    spill_kernel<<<16, TPB>>>(2, edge_row, edge_col, edge_val, out2);
}

// round 4
// speedup vs baseline: 2.4763x; 1.0657x over previous
#include <cuda_runtime.h>
#include <cuda_bf16.h>

// LightGCN 3-layer: padded-ELL build (once) + 3x warp-per-row SpMM.
// Propagated embeddings stored bf16 (halves the L2 gather traffic);
// accumulator and outputs stay fp32. No atomics in the hot path.
// out = [emb0 (N*D fp32) | (emb0+y1+y2+y3)/4 fp32]

#define U_ROWS 100000
#define I_ROWS 50000
#define N_NODES (U_ROWS + I_ROWS)
#define EMB_D 64
#define TOTAL_F (N_NODES * EMB_D)
#define TOTAL_V4 (TOTAL_F / 4)
#define PAD 64
#define SPILL_MAX (1 << 20)

__device__ __nv_bfloat16 g_xA[TOTAL_F];            // propagated x (ping)
__device__ __nv_bfloat16 g_xB[TOTAL_F];            // propagated x (pong)
__device__ float         g_acc[TOTAL_F];           // fp32 running sum
__device__ int2          g_slots[(size_t)N_NODES * PAD];  // {col, val bits}
__device__ int           g_cnt[N_NODES];
__device__ int           g_spill[SPILL_MAX];
__device__ int           g_spill_cnt;

// ---------------------------------------------------------------------------
// init: g_xA = bf16(emb0); acc = emb0; out[0:TOTAL_F] = emb0; cnt=0
// ---------------------------------------------------------------------------
__global__ void init_kernel(const float4* __restrict__ u,
                            const float4* __restrict__ it,
                            float4* __restrict__ out) {
    int i = blockIdx.x * blockDim.x + threadIdx.x;
    if (i == 0) g_spill_cnt = 0;
    if (i < N_NODES) g_cnt[i] = 0;
    if (i >= TOTAL_V4) return;
    const int u_v4 = U_ROWS * EMB_D / 4;
    float4 v = (i < u_v4) ? u[i] : it[i - u_v4];
    ((float4*)g_acc)[i] = v;
    out[i] = v;
    __nv_bfloat162 lo = __floats2bfloat162_rn(v.x, v.y);
    __nv_bfloat162 hi = __floats2bfloat162_rn(v.z, v.w);
    __nv_bfloat162* xa = (__nv_bfloat162*)g_xA;
    xa[2 * i]     = lo;
    xa[2 * i + 1] = hi;
}

// ---------------------------------------------------------------------------
// build: scatter each edge into its row's ELL bucket (order-free)
// ---------------------------------------------------------------------------
__global__ void build_kernel(const int*   __restrict__ rows,
                             const int*   __restrict__ cols,
                             const float* __restrict__ vals,
                             int nnz) {
    int e = blockIdx.x * blockDim.x + threadIdx.x;
    if (e >= nnz) return;
    int r = rows[e];
    int pos = atomicAdd(&g_cnt[r], 1);
    if (pos < PAD) {
        g_slots[(size_t)r * PAD + pos] = make_int2(cols[e], __float_as_int(vals[e]));
    } else {
        int s = atomicAdd(&g_spill_cnt, 1);
        if (s < SPILL_MAX) g_spill[s] = e;
    }
}

// ---------------------------------------------------------------------------
// spmm: one warp per row. y[r] = sum val * x[col] (fp32 accum, bf16 gather).
//   mode 0: x=g_xA, write bf16 y -> g_xB, acc += y
//   mode 1: x=g_xB, write bf16 y -> g_xA, acc += y
//   mode 2: x=g_xA, out2[r] = (acc[r] + y) * 0.25   (y not stored)
// ---------------------------------------------------------------------------
__global__ __launch_bounds__(256) void spmm_ell_kernel(int mode,
                                                       float2* __restrict__ out2) {
    int gw   = (blockIdx.x * blockDim.x + threadIdx.x) >> 5;
    int lane = threadIdx.x & 31;
    if (gw >= N_NODES) return;

    const __nv_bfloat162* __restrict__ xv =
        (mode == 1) ? (const __nv_bfloat162*)g_xB : (const __nv_bfloat162*)g_xA;

    int cnt = g_cnt[gw];
    cnt = min(cnt, PAD);
    const int2* sl = g_slots + (size_t)gw * PAD;

    float ax = 0.f, ay = 0.f;
    int base = 0;
    for (; base + 32 <= cnt; base += 32) {
        int2 s = sl[base + lane];
        #pragma unroll
        for (int k = 0; k < 32; k++) {
            int   c = __shfl_sync(0xffffffffu, s.x, k);
            float v = __int_as_float(__shfl_sync(0xffffffffu, s.y, k));
            float2 f = __bfloat1622float2(xv[c * 32 + lane]);
            ax = fmaf(v, f.x, ax);
            ay = fmaf(v, f.y, ay);
        }
    }
    int rem = cnt - base;
    if (rem > 0) {
        int2 s = (lane < rem) ? sl[base + lane] : make_int2(0, 0);
        #pragma unroll 4
        for (int k = 0; k < rem; k++) {
            int   c = __shfl_sync(0xffffffffu, s.x, k);
            float v = __int_as_float(__shfl_sync(0xffffffffu, s.y, k));
            float2 f = __bfloat1622float2(xv[c * 32 + lane]);
            ax = fmaf(v, f.x, ax);
            ay = fmaf(v, f.y, ay);
        }
    }

    int off = gw * 32 + lane;
    if (mode == 2) {
        float2 a = ((const float2*)g_acc)[off];
        out2[off] = make_float2((a.x + ax) * 0.25f, (a.y + ay) * 0.25f);
    } else {
        __nv_bfloat162* xn = (mode == 0) ? (__nv_bfloat162*)g_xB
                                         : (__nv_bfloat162*)g_xA;
        xn[off] = __floats2bfloat162_rn(ax, ay);
        float2 a = ((float2*)g_acc)[off];
        ((float2*)g_acc)[off] = make_float2(a.x + ax, a.y + ay);
    }
}

// ---------------------------------------------------------------------------
// spill: ELL-overflow edges (rare; correctness net). Runs after each spmm.
//   mode 0: x=g_xA; g_xB[r]+=bf16(d); acc[r]+=d
//   mode 1: x=g_xB; g_xA[r]+=bf16(d); acc[r]+=d
//   mode 2: x=g_xA; out2[r] += d*0.25
// ---------------------------------------------------------------------------
__global__ void spill_kernel(int mode,
                             const int*   __restrict__ rows,
                             const int*   __restrict__ cols,
                             const float* __restrict__ vals,
                             float* __restrict__ out2) {
    int n = g_spill_cnt;
    if (n > SPILL_MAX) n = SPILL_MAX;
    const __nv_bfloat16* x = (mode == 1) ? g_xB : g_xA;
    for (int s = blockIdx.x * blockDim.x + threadIdx.x; s < n;
         s += gridDim.x * blockDim.x) {
        int e = g_spill[s];
        int r = rows[e], c = cols[e];
        float v = vals[e];
        for (int d = 0; d < EMB_D; d += 2) {
            float dx = v * __bfloat162float(x[c * EMB_D + d]);
            float dy = v * __bfloat162float(x[c * EMB_D + d + 1]);
            if (mode == 2) {
                atomicAdd(&out2[r * EMB_D + d],     dx * 0.25f);
                atomicAdd(&out2[r * EMB_D + d + 1], dy * 0.25f);
            } else {
                atomicAdd(&g_acc[r * EMB_D + d],     dx);
                atomicAdd(&g_acc[r * EMB_D + d + 1], dy);
                __nv_bfloat162* xn = (__nv_bfloat162*)
                    ((mode == 0) ? &g_xB[r * EMB_D + d] : &g_xA[r * EMB_D + d]);
                atomicAdd(xn, __floats2bfloat162_rn(dx, dy));
            }
        }
    }
}

extern "C" void kernel_launch(void* const* d_in, const int* in_sizes, int n_in,
                              void* d_out, int out_size) {
    const float* user_emb = (const float*)d_in[0];
    const float* item_emb = (const float*)d_in[1];
    const float* edge_val = (const float*)d_in[2];
    const int*   edge_row = (const int*)d_in[3];
    const int*   edge_col = (const int*)d_in[4];
    const int nnz = in_sizes[2];

    float* out  = (float*)d_out;
    float* out2 = out + TOTAL_F;

    const int TPB = 256;
    const int init_blocks  = (TOTAL_V4 + TPB - 1) / TPB;
    const int build_blocks = (nnz + TPB - 1) / TPB;
    const int spmm_blocks  = (N_NODES * 32 + TPB - 1) / TPB;  // warp per row

    init_kernel<<<init_blocks, TPB>>>((const float4*)user_emb,
                                      (const float4*)item_emb,
                                      (float4*)out);

    build_kernel<<<build_blocks, TPB>>>(edge_row, edge_col, edge_val, nnz);

    // layer 1: x=xA -> y->xB(bf16), acc += y
    spmm_ell_kernel<<<spmm_blocks, TPB>>>(0, nullptr);
    spill_kernel<<<16, TPB>>>(0, edge_row, edge_col, edge_val, nullptr);

    // layer 2: x=xB -> y->xA(bf16), acc += y
    spmm_ell_kernel<<<spmm_blocks, TPB>>>(1, nullptr);
    spill_kernel<<<16, TPB>>>(1, edge_row, edge_col, edge_val, nullptr);

    // layer 3: x=xA -> out2 = (acc + y)/4
    spmm_ell_kernel<<<spmm_blocks, TPB>>>(2, (float2*)out2);
    spill_kernel<<<16, TPB>>>(2, edge_row, edge_col, edge_val, out2);
}